// round 15
// baseline (speedup 1.0000x reference)
#include <cuda_runtime.h>
#include <cstdint>

// ALIF forward scan — 6-phase register load pipeline + 48-line store bursts.
// x_seq: [T, n_flat] fp32; state v, a: [n_flat]; out spikes [T, n_flat] fp32.
// Per step: v = dv*v + x; th = th0 + beta*a; s = (v>th); v -= s*th; a = da*a + s.
//
// Thread-per-neuron, sequential T. Loads: 6-buffer rotation of 8-element
// batches; batch g+p computed from b[p], batch g+p+3 loaded into b[(p+3)%6]
// (steady 24-step lookahead, proven sufficient in R13). Stores: spikes for 6
// batches (48 steps) accumulate in registers, drained as one 48-line
// same-direction STG burst per period (R13 showed 32-line bursts beat
// interleaved stores; R14 showed smem staging kills it — stay in registers).

#define U 8        // timesteps per batch
#define PER 6      // batches per period == number of load buffers
#define BLKN 64    // threads per CTA

__device__ __forceinline__ float alif_step(float& v, float& a, float xv,
                                           float dv, float da, float th0, float beta) {
    v = fmaf(dv, v, xv);
    float th = fmaf(beta, a, th0);
    float s = (v > th) ? 1.0f : 0.0f;
    v = fmaf(-s, th, v);
    a = fmaf(da, a, s);
    return s;
}

__global__ __launch_bounds__(BLKN)
void ALIF_24309514895931_kernel(const float* __restrict__ x,
                                const float* __restrict__ v0,
                                const float* __restrict__ a0,
                                const float* __restrict__ dv_p,
                                const float* __restrict__ da_p,
                                const float* __restrict__ th_p,
                                const float* __restrict__ beta_p,
                                float* __restrict__ out,
                                int n_flat, int T) {
    int i = blockIdx.x * BLKN + threadIdx.x;
    if (i >= n_flat) return;

    const float dv   = *dv_p;
    const float da   = *da_p;
    const float th0  = *th_p;
    const float beta = *beta_p;

    float v = v0[i];
    float a = a0[i];

    const float* xp = x + i;
    float* op = out + i;
    const unsigned int stride = (unsigned int)n_flat;

    const int nb = T / U;

    float b0[U], b1[U], b2[U], b3[U], b4[U], b5[U];
    float st[PER * U];

#define LOADBLK(buf, bi)                                                    \
    {                                                                       \
        unsigned int base = (unsigned int)(bi) * U * stride;                \
        _Pragma("unroll")                                                   \
        for (int k = 0; k < U; k++)                                         \
            (buf)[k] = __ldcs(xp + base + (unsigned int)k * stride);        \
    }

    // Compute batch into the register stage at period slot p (no stores yet).
#define COMPACC(buf, p)                                                     \
    {                                                                       \
        _Pragma("unroll")                                                   \
        for (int k = 0; k < U; k++)                                         \
            st[(p) * U + k] = alif_step(v, a, (buf)[k], dv, da, th0, beta); \
    }

    // Compute batch with immediate stores (remainder path).
#define COMPSTORE(buf, bi)                                                  \
    {                                                                       \
        unsigned int base = (unsigned int)(bi) * U * stride;                \
        _Pragma("unroll")                                                   \
        for (int k = 0; k < U; k++) {                                       \
            float s = alif_step(v, a, (buf)[k], dv, da, th0, beta);         \
            __stcs(op + base + (unsigned int)k * stride, s);                \
        }                                                                   \
    }

    int g = 0;
    if (nb >= PER) {
        // Prologue: batches 0,1,2 in flight (3-batch lookahead).
        LOADBLK(b0, 0);
        LOADBLK(b1, 1);
        LOADBLK(b2, 2);

        // Main: compute g+p from b[p]; load g+p+3 into b[(p+3)%6].
        for (; g + PER <= nb; g += PER) {
            if (g + 3 < nb) LOADBLK(b3, g + 3);
            COMPACC(b0, 0);
            if (g + 4 < nb) LOADBLK(b4, g + 4);
            COMPACC(b1, 1);
            if (g + 5 < nb) LOADBLK(b5, g + 5);
            COMPACC(b2, 2);
            if (g + 6 < nb) LOADBLK(b0, g + 6);
            COMPACC(b3, 3);
            if (g + 7 < nb) LOADBLK(b1, g + 7);
            COMPACC(b4, 4);
            if (g + 8 < nb) LOADBLK(b2, g + 8);
            COMPACC(b5, 5);

            // Drain: 48-line same-direction store burst.
            unsigned int base = (unsigned int)g * U * stride;
            #pragma unroll
            for (int j = 0; j < PER * U; j++)
                __stcs(op + base + (unsigned int)j * stride, st[j]);
        }
        // Remainder batches (<PER): resident in b0..b2 from the guarded loads
        // (rotation leaves batch g in b0, g+1 in b1, g+2 in b2).
        int r = nb - g;
        if (r > 0) COMPSTORE(b0, g);
        if (r > 1) COMPSTORE(b1, g + 1);
        if (r > 2) COMPSTORE(b2, g + 2);
        g = nb;
    }

    // Tail (nb < PER case handles everything here; plus T % U steps).
    for (int t = g * U; t < T; t++) {
        float xv = __ldcs(xp + (unsigned int)t * stride);
        float s = alif_step(v, a, xv, dv, da, th0, beta);
        __stcs(op + (unsigned int)t * stride, s);
    }
#undef LOADBLK
#undef COMPACC
#undef COMPSTORE
}

extern "C" void kernel_launch(void* const* d_in, const int* in_sizes, int n_in,
                              void* d_out, int out_size) {
    // metadata order: x_seq, v, a, decay_v, decay_a, threshold, beta, alpha
    const float* x      = (const float*)d_in[0];
    const float* v0     = (const float*)d_in[1];
    const float* a0     = (const float*)d_in[2];
    const float* dv_p   = (const float*)d_in[3];
    const float* da_p   = (const float*)d_in[4];
    const float* th_p   = (const float*)d_in[5];
    const float* beta_p = (const float*)d_in[6];
    // alpha (d_in[7]) only affects backward surrogate; unused in forward.

    int n_flat = in_sizes[1];
    int T      = in_sizes[0] / n_flat;

    float* out = (float*)d_out;

    int blocks = (n_flat + BLKN - 1) / BLKN;   // 1024 for n_flat=65536
    ALIF_24309514895931_kernel<<<blocks, BLKN>>>(
        x, v0, a0, dv_p, da_p, th_p, beta_p, out, n_flat, T);
}

// round 17
// speedup vs baseline: 1.5782x; 1.5782x over previous
#include <cuda_runtime.h>
#include <cstdint>

// ALIF forward scan — symmetric 4-phase pipeline: compute+reload per phase,
// 32-line store burst with all next-period reads already in flight.
// x_seq: [T, n_flat] fp32; state v, a: [n_flat]; out spikes [T, n_flat] fp32.
// Per step: v = dv*v + x; th = th0 + beta*a; s = (v>th); v -= s*th; a = da*a + s.
//
// R13 issued its last load two phases before the store burst, so the read
// stream drained during every 32-STG burst (periodic DRAM read bubble).
// Here each phase computes batch g+p from b[p] and immediately reloads b[p]
// with batch g+4+p; at burst time 4 batches (32 lines) of reads are in flight,
// so reads stream through the write burst. Registers unchanged vs R13
// (4x8 load buffers + 32 store stage).

#define U 8        // timesteps per batch
#define PER 4      // batches per period == load buffers
#define BLKN 64    // threads per CTA

__device__ __forceinline__ float alif_step(float& v, float& a, float xv,
                                           float dv, float da, float th0, float beta) {
    v = fmaf(dv, v, xv);
    float th = fmaf(beta, a, th0);
    float s = (v > th) ? 1.0f : 0.0f;
    v = fmaf(-s, th, v);
    a = fmaf(da, a, s);
    return s;
}

__global__ __launch_bounds__(BLKN)
void ALIF_24309514895931_kernel(const float* __restrict__ x,
                                const float* __restrict__ v0,
                                const float* __restrict__ a0,
                                const float* __restrict__ dv_p,
                                const float* __restrict__ da_p,
                                const float* __restrict__ th_p,
                                const float* __restrict__ beta_p,
                                float* __restrict__ out,
                                int n_flat, int T) {
    int i = blockIdx.x * BLKN + threadIdx.x;
    if (i >= n_flat) return;

    const float dv   = *dv_p;
    const float da   = *da_p;
    const float th0  = *th_p;
    const float beta = *beta_p;

    float v = v0[i];
    float a = a0[i];

    const float* xp = x + i;
    float* op = out + i;
    const unsigned int stride = (unsigned int)n_flat;

    const int nb = T / U;

    float b0[U], b1[U], b2[U], b3[U];
    float st[PER * U];

#define LOADBLK(buf, bi)                                                    \
    {                                                                       \
        unsigned int base = (unsigned int)(bi) * U * stride;                \
        _Pragma("unroll")                                                   \
        for (int k = 0; k < U; k++)                                         \
            (buf)[k] = __ldcs(xp + base + (unsigned int)k * stride);        \
    }

#define COMPACC(buf, p)                                                     \
    {                                                                       \
        _Pragma("unroll")                                                   \
        for (int k = 0; k < U; k++)                                         \
            st[(p) * U + k] = alif_step(v, a, (buf)[k], dv, da, th0, beta); \
    }

#define COMPSTORE(buf, bi)                                                  \
    {                                                                       \
        unsigned int base = (unsigned int)(bi) * U * stride;                \
        _Pragma("unroll")                                                   \
        for (int k = 0; k < U; k++) {                                       \
            float s = alif_step(v, a, (buf)[k], dv, da, th0, beta);         \
            __stcs(op + base + (unsigned int)k * stride, s);                \
        }                                                                   \
    }

    int g = 0;
    if (nb >= PER) {
        // Prologue: fill all 4 buffers (batches 0..3).
        LOADBLK(b0, 0);
        LOADBLK(b1, 1);
        LOADBLK(b2, 2);
        LOADBLK(b3, 3);

        // Main: phase p computes batch g+p from b[p], then reloads b[p] with
        // batch g+4+p. Store burst runs with 4 batches of reads in flight.
        for (; g + PER <= nb; g += PER) {
            COMPACC(b0, 0);
            if (g + 4 < nb) LOADBLK(b0, g + 4);
            COMPACC(b1, 1);
            if (g + 5 < nb) LOADBLK(b1, g + 5);
            COMPACC(b2, 2);
            if (g + 6 < nb) LOADBLK(b2, g + 6);
            COMPACC(b3, 3);
            if (g + 7 < nb) LOADBLK(b3, g + 7);

            // 32-line same-direction store burst.
            unsigned int base = (unsigned int)g * U * stride;
            #pragma unroll
            for (int j = 0; j < PER * U; j++)
                __stcs(op + base + (unsigned int)j * stride, st[j]);
        }
        // Remainder (<PER batches): resident in b0..b2 from the guarded loads.
        int r = nb - g;
        if (r > 0) COMPSTORE(b0, g);
        if (r > 1) COMPSTORE(b1, g + 1);
        if (r > 2) COMPSTORE(b2, g + 2);
        g = nb;
    }

    // Tail (nb < PER case plus T % U steps).
    for (int t = g * U; t < T; t++) {
        float xv = __ldcs(xp + (unsigned int)t * stride);
        float s = alif_step(v, a, xv, dv, da, th0, beta);
        __stcs(op + (unsigned int)t * stride, s);
    }
#undef LOADBLK
#undef COMPACC
#undef COMPSTORE
}

extern "C" void kernel_launch(void* const* d_in, const int* in_sizes, int n_in,
                              void* d_out, int out_size) {
    // metadata order: x_seq, v, a, decay_v, decay_a, threshold, beta, alpha
    const float* x      = (const float*)d_in[0];
    const float* v0     = (const float*)d_in[1];
    const float* a0     = (const float*)d_in[2];
    const float* dv_p   = (const float*)d_in[3];
    const float* da_p   = (const float*)d_in[4];
    const float* th_p   = (const float*)d_in[5];
    const float* beta_p = (const float*)d_in[6];
    // alpha (d_in[7]) only affects backward surrogate; unused in forward.

    int n_flat = in_sizes[1];
    int T      = in_sizes[0] / n_flat;

    float* out = (float*)d_out;

    int blocks = (n_flat + BLKN - 1) / BLKN;   // 1024 for n_flat=65536
    ALIF_24309514895931_kernel<<<blocks, BLKN>>>(
        x, v0, a0, dv_p, da_p, th_p, beta_p, out, n_flat, T);
}